// round 8
// baseline (speedup 1.0000x reference)
#include <cuda_runtime.h>
#include <cstdint>
#include <math.h>

#define Bb 64
#define Kk 256
#define Tt 64
#define Dd 768
#define Nn 1024

typedef unsigned long long ull;

// Scratch (static device globals -- no runtime allocation)
__device__ float g_ut[(size_t)Bb * Tt * Dd];       // uT[b][t][d]
__device__ float g_s[(size_t)Bb * Tt * Nn];        // scores -> alpha (in place)
__device__ float g_mp[2][(size_t)Bb * Dd * Tt];    // partial m (n-halves)
__device__ float g_c[(size_t)Bb * Kk * Tt];        // c[b][k][t]
__device__ float g_lc[Bb * Tt];
__device__ float g_le[Bb * Tt];

// ---------------------------------------------------------------------------
// helpers
// ---------------------------------------------------------------------------
__device__ __forceinline__ ull dup2(float x) {
    ull r; asm("mov.b64 %0, {%1, %1};" : "=l"(r) : "f"(x)); return r;
}
__device__ __forceinline__ void ffma2(ull& d, ull a, ull b) {
    asm("fma.rn.f32x2 %0, %1, %2, %0;" : "+l"(d) : "l"(a), "l"(b));
}
__device__ __forceinline__ float2 unpk(ull v) {
    float2 r; asm("mov.b64 {%0, %1}, %2;" : "=f"(r.x), "=f"(r.y) : "l"(v)); return r;
}
__device__ __forceinline__ void tf32_split(float x, uint32_t& hi, uint32_t& lo) {
    uint32_t h; asm("cvt.rna.tf32.f32 %0, %1;" : "=r"(h) : "f"(x));
    float r = __fsub_rn(x, __uint_as_float(h));
    uint32_t l; asm("cvt.rna.tf32.f32 %0, %1;" : "=r"(l) : "f"(r));
    hi = h; lo = l;
}
__device__ __forceinline__ void mma_tf32(float* c, const uint32_t* a, const uint32_t* b) {
    asm volatile(
        "mma.sync.aligned.m16n8k8.row.col.f32.tf32.tf32.f32 "
        "{%0,%1,%2,%3}, {%4,%5,%6,%7}, {%8,%9}, {%0,%1,%2,%3};"
        : "+f"(c[0]), "+f"(c[1]), "+f"(c[2]), "+f"(c[3])
        : "r"(a[0]), "r"(a[1]), "r"(a[2]), "r"(a[3]), "r"(b[0]), "r"(b[1]));
}

// ---------------------------------------------------------------------------
// K_u: uT[b,t,d] = gamma * sum_k W[d,k] * e[b,k,t]   (SIMT fp32)
// ---------------------------------------------------------------------------
__global__ __launch_bounds__(256) void k_u(const float* __restrict__ e,
                                           const float* __restrict__ W,
                                           const float* __restrict__ gamma) {
    __shared__ __align__(16) float Es[16][68];     // [k][t]
    __shared__ __align__(16) float Ws2[16][132];   // [k][d] transposed
    const int b  = blockIdx.y;
    const int d0 = blockIdx.x * 128;
    const int tid = threadIdx.x;
    const int tx = tid & 15, ty = tid >> 4;

    float acc[4][8];
#pragma unroll
    for (int i = 0; i < 4; i++)
#pragma unroll
        for (int j = 0; j < 8; j++) acc[i][j] = 0.0f;

    const float* eb = e + (size_t)b * Kk * Tt;
    const int er = tid >> 4, eq = (tid & 15) * 4;
    const int wd = tid >> 1;

    for (int k0 = 0; k0 < Kk; k0 += 16) {
        *(float4*)&Es[er][eq] = *(const float4*)&eb[(k0 + er) * Tt + eq];
#pragma unroll
        for (int j = 0; j < 2; j++) {
            const int kq = (tid & 1) * 2 + j;
            float4 wv = *(const float4*)&W[(size_t)(d0 + wd) * Kk + k0 + kq * 4];
            Ws2[kq * 4 + 0][wd] = wv.x; Ws2[kq * 4 + 1][wd] = wv.y;
            Ws2[kq * 4 + 2][wd] = wv.z; Ws2[kq * 4 + 3][wd] = wv.w;
        }
        __syncthreads();
#pragma unroll
        for (int kk = 0; kk < 16; kk++) {
            float a[4], bv[8];
            *(float4*)&a[0]  = *(float4*)&Es[kk][ty * 4];
            *(float4*)&bv[0] = *(float4*)&Ws2[kk][tx * 8];
            *(float4*)&bv[4] = *(float4*)&Ws2[kk][tx * 8 + 4];
#pragma unroll
            for (int i = 0; i < 4; i++)
#pragma unroll
                for (int j = 0; j < 8; j++) acc[i][j] = fmaf(a[i], bv[j], acc[i][j]);
        }
        __syncthreads();
    }

    const float g = *gamma;
    float* ub = g_ut + (size_t)b * Tt * Dd;
#pragma unroll
    for (int i = 0; i < 4; i++) {
        const int t = ty * 4 + i;
        float4 o0, o1;
        o0.x = g * acc[i][0]; o0.y = g * acc[i][1]; o0.z = g * acc[i][2]; o0.w = g * acc[i][3];
        o1.x = g * acc[i][4]; o1.y = g * acc[i][5]; o1.z = g * acc[i][6]; o1.w = g * acc[i][7];
        *(float4*)&ub[(size_t)t * Dd + d0 + tx * 8]     = o0;
        *(float4*)&ub[(size_t)t * Dd + d0 + tx * 8 + 4] = o1;
    }
}

// ---------------------------------------------------------------------------
// K_s (mma.sync tf32, 3-term hi/lo split):
// s[b,t,n] = sum_d uT[t,d] * f[d,n]
// block 256 thr, tile 64t x 128n, K-chunk 16 d, 48 chunks
// warp w: mb=(w&1)*32 (t), nb=(w>>1)*32 (n)
// ---------------------------------------------------------------------------
__global__ __launch_bounds__(256) void k_s(const float* __restrict__ f) {
    __shared__ uint32_t Uhi[64][20];    // [t][d-chunk]
    __shared__ uint32_t Ulo[64][20];
    __shared__ uint32_t Fhi[16][132];   // [d-chunk][n]
    __shared__ uint32_t Flo[16][132];
    const int b  = blockIdx.y;
    const int n0 = blockIdx.x * 128;
    const int tid = threadIdx.x;
    const int w = tid >> 5, lane = tid & 31;
    const int g = lane >> 2, tig = lane & 3;
    const int mb = (w & 1) * 32, nb = (w >> 1) * 32;

    float acc[2][4][4];
#pragma unroll
    for (int mt = 0; mt < 2; mt++)
#pragma unroll
        for (int nt = 0; nt < 4; nt++)
#pragma unroll
            for (int i = 0; i < 4; i++) acc[mt][nt][i] = 0.0f;

    const float* ub = g_ut + (size_t)b * Tt * Dd;
    const float* fb = f    + (size_t)b * Dd * Nn;

    const int ut_t = tid >> 2;          // 0..63
    const int ut_d = (tid & 3) * 4;     // 0,4,8,12
    const int fs_d = tid >> 4;          // 0..15
    const int fs_n = (tid & 15) * 8;    // 0..120

    float4 ua, fa0, fa1;
    ua  = *(const float4*)&ub[(size_t)ut_t * Dd + ut_d];
    fa0 = *(const float4*)&fb[(size_t)fs_d * Nn + n0 + fs_n];
    fa1 = *(const float4*)&fb[(size_t)fs_d * Nn + n0 + fs_n + 4];

    for (int c = 0; c < 48; c++) {
        __syncthreads();
        {
            uint4 uh, ul;
            tf32_split(ua.x, uh.x, ul.x); tf32_split(ua.y, uh.y, ul.y);
            tf32_split(ua.z, uh.z, ul.z); tf32_split(ua.w, uh.w, ul.w);
            *(uint4*)&Uhi[ut_t][ut_d] = uh;
            *(uint4*)&Ulo[ut_t][ut_d] = ul;
            uint4 fh0, fl0, fh1, fl1;
            tf32_split(fa0.x, fh0.x, fl0.x); tf32_split(fa0.y, fh0.y, fl0.y);
            tf32_split(fa0.z, fh0.z, fl0.z); tf32_split(fa0.w, fh0.w, fl0.w);
            tf32_split(fa1.x, fh1.x, fl1.x); tf32_split(fa1.y, fh1.y, fl1.y);
            tf32_split(fa1.z, fh1.z, fl1.z); tf32_split(fa1.w, fh1.w, fl1.w);
            *(uint4*)&Fhi[fs_d][fs_n]     = fh0;
            *(uint4*)&Fhi[fs_d][fs_n + 4] = fh1;
            *(uint4*)&Flo[fs_d][fs_n]     = fl0;
            *(uint4*)&Flo[fs_d][fs_n + 4] = fl1;
        }
        __syncthreads();
        if (c < 47) {
            const int d0n = (c + 1) * 16;
            ua  = *(const float4*)&ub[(size_t)ut_t * Dd + d0n + ut_d];
            fa0 = *(const float4*)&fb[(size_t)(d0n + fs_d) * Nn + n0 + fs_n];
            fa1 = *(const float4*)&fb[(size_t)(d0n + fs_d) * Nn + n0 + fs_n + 4];
        }
#pragma unroll
        for (int ks = 0; ks < 2; ks++) {
            const int k0 = ks * 8;
            uint32_t ah[2][4], al[2][4];
#pragma unroll
            for (int mt = 0; mt < 2; mt++) {
                const int r0 = mb + mt * 16 + g;
                ah[mt][0] = Uhi[r0][k0 + tig];         al[mt][0] = Ulo[r0][k0 + tig];
                ah[mt][1] = Uhi[r0 + 8][k0 + tig];     al[mt][1] = Ulo[r0 + 8][k0 + tig];
                ah[mt][2] = Uhi[r0][k0 + tig + 4];     al[mt][2] = Ulo[r0][k0 + tig + 4];
                ah[mt][3] = Uhi[r0 + 8][k0 + tig + 4]; al[mt][3] = Ulo[r0 + 8][k0 + tig + 4];
            }
#pragma unroll
            for (int nt = 0; nt < 4; nt++) {
                const int col = nb + nt * 8 + g;
                uint32_t bh[2], bl[2];
                bh[0] = Fhi[k0 + tig][col];     bh[1] = Fhi[k0 + tig + 4][col];
                bl[0] = Flo[k0 + tig][col];     bl[1] = Flo[k0 + tig + 4][col];
#pragma unroll
                for (int mt = 0; mt < 2; mt++) {
                    mma_tf32(acc[mt][nt], ah[mt], bh);
                    mma_tf32(acc[mt][nt], ah[mt], bl);
                    mma_tf32(acc[mt][nt], al[mt], bh);
                }
            }
        }
    }

    float* sb = g_s + (size_t)b * Tt * Nn;
#pragma unroll
    for (int mt = 0; mt < 2; mt++) {
        const int r0 = mb + mt * 16 + g;
#pragma unroll
        for (int nt = 0; nt < 4; nt++) {
            const int col = n0 + nb + nt * 8 + 2 * tig;
            float2 lo, hi;
            lo.x = acc[mt][nt][0]; lo.y = acc[mt][nt][1];
            hi.x = acc[mt][nt][2]; hi.y = acc[mt][nt][3];
            *(float2*)&sb[(size_t)r0 * Nn + col]       = lo;
            *(float2*)&sb[(size_t)(r0 + 8) * Nn + col] = hi;
        }
    }
}

// ---------------------------------------------------------------------------
// K3: softmax over n (1024), in-place on g_s
// ---------------------------------------------------------------------------
__global__ __launch_bounds__(256) void k3_softmax() {
    const int row = blockIdx.x;
    float* s = g_s + (size_t)row * Nn;
    const int tid = threadIdx.x;
    const int w = tid >> 5, l = tid & 31;

    float4 x = *(float4*)&s[tid * 4];
    float m = fmaxf(fmaxf(x.x, x.y), fmaxf(x.z, x.w));
#pragma unroll
    for (int o = 16; o > 0; o >>= 1) m = fmaxf(m, __shfl_xor_sync(0xffffffffu, m, o));

    __shared__ float redm[8];
    __shared__ float reds[8];
    if (l == 0) redm[w] = m;
    __syncthreads();
    float mx = redm[0];
#pragma unroll
    for (int i = 1; i < 8; i++) mx = fmaxf(mx, redm[i]);

    float e0 = __expf(x.x - mx), e1 = __expf(x.y - mx);
    float e2 = __expf(x.z - mx), e3 = __expf(x.w - mx);
    float sum = e0 + e1 + e2 + e3;
#pragma unroll
    for (int o = 16; o > 0; o >>= 1) sum += __shfl_xor_sync(0xffffffffu, sum, o);
    if (l == 0) reds[w] = sum;
    __syncthreads();
    float tot = 0.0f;
#pragma unroll
    for (int i = 0; i < 8; i++) tot += reds[i];
    const float inv = 1.0f / tot;

    float4 o;
    o.x = e0 * inv; o.y = e1 * inv; o.z = e2 * inv; o.w = e3 * inv;
    *(float4*)&s[tid * 4] = o;
}

// ---------------------------------------------------------------------------
// K_m (mma.sync tf32, 3-term hi/lo split):
// m_part[nh][b,d,t] = sum_{n in half} f[d,n] * alpha[t,n]
// block 256 thr, tile 128d x 64t, K-chunk 16 n, 32 chunks (Nn/2=512)
// warp w: mb=(w&3)*32 (d), nb=(w>>2)*32 (t)
// ---------------------------------------------------------------------------
__global__ __launch_bounds__(256) void k_m(const float* __restrict__ f) {
    __shared__ uint32_t Ahi[128][20];
    __shared__ uint32_t Alo[128][20];
    __shared__ uint32_t Bhi[16][68];
    __shared__ uint32_t Blo[16][68];
    const int b  = blockIdx.z;
    const int nh = blockIdx.y;
    const int d0 = blockIdx.x * 128;
    const int tid = threadIdx.x;
    const int w = tid >> 5, lane = tid & 31;
    const int g = lane >> 2, tig = lane & 3;
    const int mb = (w & 3) * 32, nb = (w >> 2) * 32;

    float acc[2][4][4];
#pragma unroll
    for (int mt = 0; mt < 2; mt++)
#pragma unroll
        for (int nt = 0; nt < 4; nt++)
#pragma unroll
            for (int i = 0; i < 4; i++) acc[mt][nt][i] = 0.0f;

    const float* fb = f   + (size_t)b * Dd * Nn + (size_t)nh * (Nn / 2);
    const float* ab = g_s + (size_t)b * Tt * Nn + (size_t)nh * (Nn / 2);

    const int fa_d = tid >> 1;           // 0..127
    const int fa_n = (tid & 1) * 8;      // 0/8
    const int al_t = tid & 63;           // 0..63
    const int al_n = (tid >> 6) * 4;     // 0,4,8,12

    float4 fv0, fv1, av;
    fv0 = *(const float4*)&fb[(size_t)(d0 + fa_d) * Nn + fa_n];
    fv1 = *(const float4*)&fb[(size_t)(d0 + fa_d) * Nn + fa_n + 4];
    av  = *(const float4*)&ab[(size_t)al_t * Nn + al_n];

    for (int c = 0; c < 32; c++) {
        __syncthreads();
        {
            uint4 h0, l0, h1, l1;
            tf32_split(fv0.x, h0.x, l0.x); tf32_split(fv0.y, h0.y, l0.y);
            tf32_split(fv0.z, h0.z, l0.z); tf32_split(fv0.w, h0.w, l0.w);
            tf32_split(fv1.x, h1.x, l1.x); tf32_split(fv1.y, h1.y, l1.y);
            tf32_split(fv1.z, h1.z, l1.z); tf32_split(fv1.w, h1.w, l1.w);
            *(uint4*)&Ahi[fa_d][fa_n]     = h0;
            *(uint4*)&Ahi[fa_d][fa_n + 4] = h1;
            *(uint4*)&Alo[fa_d][fa_n]     = l0;
            *(uint4*)&Alo[fa_d][fa_n + 4] = l1;
            uint32_t bh[4], bl[4];
            tf32_split(av.x, bh[0], bl[0]); tf32_split(av.y, bh[1], bl[1]);
            tf32_split(av.z, bh[2], bl[2]); tf32_split(av.w, bh[3], bl[3]);
#pragma unroll
            for (int j = 0; j < 4; j++) {
                Bhi[al_n + j][al_t] = bh[j];
                Blo[al_n + j][al_t] = bl[j];
            }
        }
        __syncthreads();
        if (c < 31) {
            const int n0n = (c + 1) * 16;
            fv0 = *(const float4*)&fb[(size_t)(d0 + fa_d) * Nn + n0n + fa_n];
            fv1 = *(const float4*)&fb[(size_t)(d0 + fa_d) * Nn + n0n + fa_n + 4];
            av  = *(const float4*)&ab[(size_t)al_t * Nn + n0n + al_n];
        }
#pragma unroll
        for (int ks = 0; ks < 2; ks++) {
            const int k0 = ks * 8;
            uint32_t ah[2][4], al[2][4];
#pragma unroll
            for (int mt = 0; mt < 2; mt++) {
                const int r0 = mb + mt * 16 + g;
                ah[mt][0] = Ahi[r0][k0 + tig];     al[mt][0] = Alo[r0][k0 + tig];
                ah[mt][1] = Ahi[r0 + 8][k0 + tig]; al[mt][1] = Alo[r0 + 8][k0 + tig];
                ah[mt][2] = Ahi[r0][k0 + tig + 4]; al[mt][2] = Alo[r0][k0 + tig + 4];
                ah[mt][3] = Ahi[r0 + 8][k0 + tig + 4]; al[mt][3] = Alo[r0 + 8][k0 + tig + 4];
            }
#pragma unroll
            for (int nt = 0; nt < 4; nt++) {
                const int col = nb + nt * 8 + g;
                uint32_t bh[2], bl[2];
                bh[0] = Bhi[k0 + tig][col];     bh[1] = Bhi[k0 + tig + 4][col];
                bl[0] = Blo[k0 + tig][col];     bl[1] = Blo[k0 + tig + 4][col];
#pragma unroll
                for (int mt = 0; mt < 2; mt++) {
                    mma_tf32(acc[mt][nt], ah[mt], bh);
                    mma_tf32(acc[mt][nt], ah[mt], bl);
                    mma_tf32(acc[mt][nt], al[mt], bh);
                }
            }
        }
    }

    float* mb_out = g_mp[nh] + (size_t)b * Dd * Tt;
#pragma unroll
    for (int mt = 0; mt < 2; mt++) {
        const int r0 = d0 + mb + mt * 16 + g;
#pragma unroll
        for (int nt = 0; nt < 4; nt++) {
            const int col = nb + nt * 8 + 2 * tig;
            float2 lo, hi;
            lo.x = acc[mt][nt][0]; lo.y = acc[mt][nt][1];
            hi.x = acc[mt][nt][2]; hi.y = acc[mt][nt][3];
            *(float2*)&mb_out[(size_t)r0 * Tt + col]       = lo;
            *(float2*)&mb_out[(size_t)(r0 + 8) * Tt + col] = hi;
        }
    }
}

// ---------------------------------------------------------------------------
// K_c: c[b,k,t] = sum_d W[d,k] * (m0+m1)[b,d,t] + bias[k]   (FFMA2)
// ---------------------------------------------------------------------------
__global__ __launch_bounds__(256) void k_c(const float* __restrict__ W,
                                           const float* __restrict__ bias) {
    __shared__ __align__(16) float Wt[8][68];
    __shared__ __align__(16) float Ms[8][68];
    const int b  = blockIdx.y;
    const int k0 = blockIdx.x * 64;
    const int tid = threadIdx.x;
    const int tx = tid & 15, ty = tid >> 4;

    ull acc[4][2];
#pragma unroll
    for (int i = 0; i < 4; i++) { acc[i][0] = 0ULL; acc[i][1] = 0ULL; }

    const float* mb0 = g_mp[0] + (size_t)b * Dd * Tt;
    const float* mb1 = g_mp[1] + (size_t)b * Dd * Tt;
    const int dd = tid >> 5;
    const int cc = (tid & 31) * 2;

    for (int d0 = 0; d0 < Dd; d0 += 8) {
        *(float2*)&Wt[dd][cc] = *(const float2*)&W[(size_t)(d0 + dd) * Kk + k0 + cc];
        float2 ma = *(const float2*)&mb0[(size_t)(d0 + dd) * Tt + cc];
        float2 mc = *(const float2*)&mb1[(size_t)(d0 + dd) * Tt + cc];
        Ms[dd][cc] = ma.x + mc.x; Ms[dd][cc + 1] = ma.y + mc.y;
        __syncthreads();
#pragma unroll
        for (int d = 0; d < 8; d++) {
            float4 a4 = *(float4*)&Wt[d][ty * 4];
            ull ad[4] = {dup2(a4.x), dup2(a4.y), dup2(a4.z), dup2(a4.w)};
            ulonglong2 bp = *(ulonglong2*)&Ms[d][tx * 4];
#pragma unroll
            for (int i = 0; i < 4; i++) {
                ffma2(acc[i][0], ad[i], bp.x);
                ffma2(acc[i][1], ad[i], bp.y);
            }
        }
        __syncthreads();
    }

    float* cb = g_c + (size_t)b * Kk * Tt;
#pragma unroll
    for (int i = 0; i < 4; i++) {
        const int k = k0 + ty * 4 + i;
        const float bi = bias[k];
        float2 p0 = unpk(acc[i][0]), p1 = unpk(acc[i][1]);
        float4 o;
        o.x = p0.x + bi; o.y = p0.y + bi; o.z = p1.x + bi; o.w = p1.y + bi;
        *(float4*)&cb[(size_t)k * Tt + tx * 4] = o;
    }
}

// ---------------------------------------------------------------------------
// K5: per-token norms
// ---------------------------------------------------------------------------
__global__ __launch_bounds__(256) void k5_norms(const float* __restrict__ e) {
    __shared__ float re[4][64];
    __shared__ float rc[4][64];
    const int b = blockIdx.x;
    const int tid = threadIdx.x;
    const int t = tid & 63, q = tid >> 6;
    const float* eb = e   + (size_t)b * Kk * Tt;
    const float* cb = g_c + (size_t)b * Kk * Tt;
    float se = 0.0f, sc = 0.0f;
    for (int k = q * 64; k < q * 64 + 64; k++) {
        float x = eb[k * Tt + t]; se = fmaf(x, x, se);
        float y = cb[k * Tt + t]; sc = fmaf(y, y, sc);
    }
    re[q][t] = se; rc[q][t] = sc;
    __syncthreads();
    if (tid < 64) {
        float a = re[0][tid] + re[1][tid] + re[2][tid] + re[3][tid];
        float d = rc[0][tid] + rc[1][tid] + rc[2][tid] + rc[3][tid];
        g_le[b * Tt + tid] = sqrtf(a);
        g_lc[b * Tt + tid] = sqrtf(d);
    }
}

// ---------------------------------------------------------------------------
// K6: cos[b,i,j] = (sum_k c[b,k,i]*e[b,k,j]) / (lc[i]*le[j])
// ---------------------------------------------------------------------------
__global__ __launch_bounds__(256) void k6_cos(const float* __restrict__ e,
                                              float* __restrict__ out) {
    __shared__ __align__(16) float Cs[16][36];
    __shared__ __align__(16) float Es[16][68];
    const int ih = blockIdx.x;
    const int b  = blockIdx.y;
    const int tid = threadIdx.x;
    const int tx = tid & 15, ty = tid >> 4;

    ull acc[2][2];
    acc[0][0] = acc[0][1] = acc[1][0] = acc[1][1] = 0ULL;

    const float* cb = g_c + (size_t)b * Kk * Tt;
    const float* eb = e   + (size_t)b * Kk * Tt;
    const int lk = tid >> 4;
    const int ltE = (tid & 15) * 4;
    const int ltC = (tid & 15) * 2;

    for (int k0 = 0; k0 < Kk; k0 += 16) {
        *(float2*)&Cs[lk][ltC] = *(const float2*)&cb[(k0 + lk) * Tt + ih * 32 + ltC];
        *(float4*)&Es[lk][ltE] = *(const float4*)&eb[(k0 + lk) * Tt + ltE];
        __syncthreads();
#pragma unroll
        for (int kk = 0; kk < 16; kk++) {
            float2 a2 = *(float2*)&Cs[kk][ty * 2];
            ull ad[2] = {dup2(a2.x), dup2(a2.y)};
            ulonglong2 bp = *(ulonglong2*)&Es[kk][tx * 4];
#pragma unroll
            for (int i = 0; i < 2; i++) {
                ffma2(acc[i][0], ad[i], bp.x);
                ffma2(acc[i][1], ad[i], bp.y);
            }
        }
        __syncthreads();
    }

    float lci[2], lej[4];
#pragma unroll
    for (int i = 0; i < 2; i++) lci[i] = g_lc[b * Tt + ih * 32 + ty * 2 + i];
#pragma unroll
    for (int j = 0; j < 4; j++) lej[j] = g_le[b * Tt + tx * 4 + j];

#pragma unroll
    for (int i = 0; i < 2; i++) {
        const int irow = ih * 32 + ty * 2 + i;
        float2 p0 = unpk(acc[i][0]), p1 = unpk(acc[i][1]);
        float4 o;
        o.x = p0.x / (lci[i] * lej[0]);
        o.y = p0.y / (lci[i] * lej[1]);
        o.z = p1.x / (lci[i] * lej[2]);
        o.w = p1.y / (lci[i] * lej[3]);
        *(float4*)&out[((size_t)b * Tt + irow) * Tt + tx * 4] = o;
    }
}

// ---------------------------------------------------------------------------
extern "C" void kernel_launch(void* const* d_in, const int* in_sizes, int n_in,
                              void* d_out, int out_size) {
    const float* e     = (const float*)d_in[0];
    const float* f     = (const float*)d_in[1];
    const float* gamma = (const float*)d_in[2];
    const float* W     = (const float*)d_in[3];
    const float* bias  = (const float*)d_in[4];
    float* out = (float*)d_out;

    k_u<<<dim3(Dd / 128, Bb), 256>>>(e, W, gamma);
    k_s<<<dim3(Nn / 128, Bb), 256>>>(f);
    k3_softmax<<<Bb * Tt, 256>>>();
    k_m<<<dim3(Dd / 128, 2, Bb), 256>>>(f);
    k_c<<<dim3(Kk / 64, Bb), 256>>>(W, bias);
    k5_norms<<<Bb, 256>>>(e);
    k6_cos<<<dim3(2, Bb), 256>>>(e, out);
}

// round 10
// speedup vs baseline: 1.0234x; 1.0234x over previous
#include <cuda_runtime.h>
#include <cstdint>
#include <math.h>

#define Bb 64
#define Kk 256
#define Tt 64
#define Dd 768
#define Nn 1024

typedef unsigned long long ull;

// Scratch (static device globals -- no runtime allocation)
__device__ float g_ut[(size_t)Bb * Tt * Dd];       // uT[b][t][d]
__device__ float g_s[(size_t)Bb * Tt * Nn];        // scores -> alpha (in place)
__device__ float g_mp[2][(size_t)Bb * Dd * Tt];    // partial m (n-halves)
__device__ float g_c[(size_t)Bb * Kk * Tt];        // c[b][k][t]
__device__ float g_lc[Bb * Tt];
__device__ float g_le[Bb * Tt];

// ---------------------------------------------------------------------------
// helpers
// ---------------------------------------------------------------------------
__device__ __forceinline__ ull dup2(float x) {
    ull r; asm("mov.b64 %0, {%1, %1};" : "=l"(r) : "f"(x)); return r;
}
__device__ __forceinline__ void ffma2(ull& d, ull a, ull b) {
    asm("fma.rn.f32x2 %0, %1, %2, %0;" : "+l"(d) : "l"(a), "l"(b));
}
__device__ __forceinline__ float2 unpk(ull v) {
    float2 r; asm("mov.b64 {%0, %1}, %2;" : "=f"(r.x), "=f"(r.y) : "l"(v)); return r;
}
__device__ __forceinline__ void tf32_split(float x, uint32_t& hi, uint32_t& lo) {
    uint32_t h; asm("cvt.rna.tf32.f32 %0, %1;" : "=r"(h) : "f"(x));
    float r = __fsub_rn(x, __uint_as_float(h));
    uint32_t l; asm("cvt.rna.tf32.f32 %0, %1;" : "=r"(l) : "f"(r));
    hi = h; lo = l;
}
__device__ __forceinline__ void mma_tf32(float* c, const uint32_t* a, const uint32_t* b) {
    asm volatile(
        "mma.sync.aligned.m16n8k8.row.col.f32.tf32.tf32.f32 "
        "{%0,%1,%2,%3}, {%4,%5,%6,%7}, {%8,%9}, {%0,%1,%2,%3};"
        : "+f"(c[0]), "+f"(c[1]), "+f"(c[2]), "+f"(c[3])
        : "r"(a[0]), "r"(a[1]), "r"(a[2]), "r"(a[3]), "r"(b[0]), "r"(b[1]));
}
__device__ __forceinline__ void ldsm4(uint32_t* r, uint32_t a) {
    asm volatile("ldmatrix.sync.aligned.m8n8.x4.shared.b16 {%0,%1,%2,%3}, [%4];"
        : "=r"(r[0]), "=r"(r[1]), "=r"(r[2]), "=r"(r[3]) : "r"(a));
}
__device__ __forceinline__ uint32_t s2u(const void* p) {
    return (uint32_t)__cvta_generic_to_shared(p);
}

// ---------------------------------------------------------------------------
// K_u: uT[b,t,d] = gamma * sum_k W[d,k] * e[b,k,t]   (SIMT fp32)
// ---------------------------------------------------------------------------
__global__ __launch_bounds__(256) void k_u(const float* __restrict__ e,
                                           const float* __restrict__ W,
                                           const float* __restrict__ gamma) {
    __shared__ __align__(16) float Es[16][68];     // [k][t]
    __shared__ __align__(16) float Ws2[16][132];   // [k][d] transposed
    const int b  = blockIdx.y;
    const int d0 = blockIdx.x * 128;
    const int tid = threadIdx.x;
    const int tx = tid & 15, ty = tid >> 4;

    float acc[4][8];
#pragma unroll
    for (int i = 0; i < 4; i++)
#pragma unroll
        for (int j = 0; j < 8; j++) acc[i][j] = 0.0f;

    const float* eb = e + (size_t)b * Kk * Tt;
    const int er = tid >> 4, eq = (tid & 15) * 4;
    const int wd = tid >> 1;

    for (int k0 = 0; k0 < Kk; k0 += 16) {
        *(float4*)&Es[er][eq] = *(const float4*)&eb[(k0 + er) * Tt + eq];
#pragma unroll
        for (int j = 0; j < 2; j++) {
            const int kq = (tid & 1) * 2 + j;
            float4 wv = *(const float4*)&W[(size_t)(d0 + wd) * Kk + k0 + kq * 4];
            Ws2[kq * 4 + 0][wd] = wv.x; Ws2[kq * 4 + 1][wd] = wv.y;
            Ws2[kq * 4 + 2][wd] = wv.z; Ws2[kq * 4 + 3][wd] = wv.w;
        }
        __syncthreads();
#pragma unroll
        for (int kk = 0; kk < 16; kk++) {
            float a[4], bv[8];
            *(float4*)&a[0]  = *(float4*)&Es[kk][ty * 4];
            *(float4*)&bv[0] = *(float4*)&Ws2[kk][tx * 8];
            *(float4*)&bv[4] = *(float4*)&Ws2[kk][tx * 8 + 4];
#pragma unroll
            for (int i = 0; i < 4; i++)
#pragma unroll
                for (int j = 0; j < 8; j++) acc[i][j] = fmaf(a[i], bv[j], acc[i][j]);
        }
        __syncthreads();
    }

    const float g = *gamma;
    float* ub = g_ut + (size_t)b * Tt * Dd;
#pragma unroll
    for (int i = 0; i < 4; i++) {
        const int t = ty * 4 + i;
        float4 o0, o1;
        o0.x = g * acc[i][0]; o0.y = g * acc[i][1]; o0.z = g * acc[i][2]; o0.w = g * acc[i][3];
        o1.x = g * acc[i][4]; o1.y = g * acc[i][5]; o1.z = g * acc[i][6]; o1.w = g * acc[i][7];
        *(float4*)&ub[(size_t)t * Dd + d0 + tx * 8]     = o0;
        *(float4*)&ub[(size_t)t * Dd + d0 + tx * 8 + 4] = o1;
    }
}

// ---------------------------------------------------------------------------
// K_s (mma tf32, 3-term split, ldmatrix A, scalar B, double-buffered):
// s[b,t,n] = sum_d uT[t,d] * f[d,n]
// block 256 thr, tile 64t x 128n, K-chunk 16 d, 48 chunks
// dynamic smem: U[2][2][64][20] + F[2][2][16][132] = 54272 B
// ---------------------------------------------------------------------------
#define KS_SMEM 54272
__global__ __launch_bounds__(256) void k_s(const float* __restrict__ f) {
    extern __shared__ uint32_t ksm[];
    uint32_t (*U)[2][64][20]  = (uint32_t(*)[2][64][20])ksm;             // 5120 words
    uint32_t (*F)[2][16][132] = (uint32_t(*)[2][16][132])(ksm + 5120);   // 8448 words
    const int b  = blockIdx.y;
    const int n0 = blockIdx.x * 128;
    const int tid = threadIdx.x;
    const int w = tid >> 5, lane = tid & 31;
    const int g = lane >> 2, tig = lane & 3;
    const int mb = (w & 1) * 32, nb = (w >> 1) * 32;
    const int a_row = (lane & 7) + 8 * ((lane >> 3) & 1);
    const int a_col = 4 * (lane >> 4);

    float acc[2][4][4];
#pragma unroll
    for (int mt = 0; mt < 2; mt++)
#pragma unroll
        for (int nt = 0; nt < 4; nt++)
#pragma unroll
            for (int i = 0; i < 4; i++) acc[mt][nt][i] = 0.0f;

    const float* ub = g_ut + (size_t)b * Tt * Dd;
    const float* fb = f    + (size_t)b * Dd * Nn;
    const int ut_t = tid >> 2, ut_d = (tid & 3) * 4;
    const int fs_d = tid >> 4, fs_n = (tid & 15) * 8;

    float4 ua, fa0, fa1;
    ua  = *(const float4*)&ub[(size_t)ut_t * Dd + ut_d];
    fa0 = *(const float4*)&fb[(size_t)fs_d * Nn + n0 + fs_n];
    fa1 = *(const float4*)&fb[(size_t)fs_d * Nn + n0 + fs_n + 4];

    // stage chunk 0 -> buf 0
    {
        uint4 uh, ul;
        tf32_split(ua.x, uh.x, ul.x); tf32_split(ua.y, uh.y, ul.y);
        tf32_split(ua.z, uh.z, ul.z); tf32_split(ua.w, uh.w, ul.w);
        *(uint4*)&U[0][0][ut_t][ut_d] = uh;
        *(uint4*)&U[0][1][ut_t][ut_d] = ul;
        uint4 fh0, fl0, fh1, fl1;
        tf32_split(fa0.x, fh0.x, fl0.x); tf32_split(fa0.y, fh0.y, fl0.y);
        tf32_split(fa0.z, fh0.z, fl0.z); tf32_split(fa0.w, fh0.w, fl0.w);
        tf32_split(fa1.x, fh1.x, fl1.x); tf32_split(fa1.y, fh1.y, fl1.y);
        tf32_split(fa1.z, fh1.z, fl1.z); tf32_split(fa1.w, fh1.w, fl1.w);
        *(uint4*)&F[0][0][fs_d][fs_n]     = fh0;
        *(uint4*)&F[0][0][fs_d][fs_n + 4] = fh1;
        *(uint4*)&F[0][1][fs_d][fs_n]     = fl0;
        *(uint4*)&F[0][1][fs_d][fs_n + 4] = fl1;
    }
    __syncthreads();

    int p = 0;
    for (int c = 0; c < 48; c++) {
        if (c < 47) {
            const int d0n = (c + 1) * 16;
            ua  = *(const float4*)&ub[(size_t)ut_t * Dd + d0n + ut_d];
            fa0 = *(const float4*)&fb[(size_t)(d0n + fs_d) * Nn + n0 + fs_n];
            fa1 = *(const float4*)&fb[(size_t)(d0n + fs_d) * Nn + n0 + fs_n + 4];
        }
        // compute buf p
        {
            const uint32_t uh_s = s2u(&U[p][0][0][0]);
            const uint32_t ul_s = s2u(&U[p][1][0][0]);
#pragma unroll
            for (int ks = 0; ks < 2; ks++) {
                const int k0 = ks * 8;
                uint32_t ah[2][4], al_[2][4];
#pragma unroll
                for (int mt = 0; mt < 2; mt++) {
                    const uint32_t off = 4u * ((mb + mt * 16 + a_row) * 20 + k0 + a_col);
                    ldsm4(ah[mt],  uh_s + off);
                    ldsm4(al_[mt], ul_s + off);
                }
#pragma unroll
                for (int nt = 0; nt < 4; nt++) {
                    const int col = nb + nt * 8 + g;
                    uint32_t bh[2], bl[2];
                    bh[0] = F[p][0][k0 + tig][col];     bh[1] = F[p][0][k0 + tig + 4][col];
                    bl[0] = F[p][1][k0 + tig][col];     bl[1] = F[p][1][k0 + tig + 4][col];
#pragma unroll
                    for (int mt = 0; mt < 2; mt++) {
                        mma_tf32(acc[mt][nt], ah[mt],  bh);
                        mma_tf32(acc[mt][nt], ah[mt],  bl);
                        mma_tf32(acc[mt][nt], al_[mt], bh);
                    }
                }
            }
        }
        if (c < 47) {
            const int q = p ^ 1;
            uint4 uh, ul;
            tf32_split(ua.x, uh.x, ul.x); tf32_split(ua.y, uh.y, ul.y);
            tf32_split(ua.z, uh.z, ul.z); tf32_split(ua.w, uh.w, ul.w);
            *(uint4*)&U[q][0][ut_t][ut_d] = uh;
            *(uint4*)&U[q][1][ut_t][ut_d] = ul;
            uint4 fh0, fl0, fh1, fl1;
            tf32_split(fa0.x, fh0.x, fl0.x); tf32_split(fa0.y, fh0.y, fl0.y);
            tf32_split(fa0.z, fh0.z, fl0.z); tf32_split(fa0.w, fh0.w, fl0.w);
            tf32_split(fa1.x, fh1.x, fl1.x); tf32_split(fa1.y, fh1.y, fl1.y);
            tf32_split(fa1.z, fh1.z, fl1.z); tf32_split(fa1.w, fh1.w, fl1.w);
            *(uint4*)&F[q][0][fs_d][fs_n]     = fh0;
            *(uint4*)&F[q][0][fs_d][fs_n + 4] = fh1;
            *(uint4*)&F[q][1][fs_d][fs_n]     = fl0;
            *(uint4*)&F[q][1][fs_d][fs_n + 4] = fl1;
        }
        __syncthreads();
        p ^= 1;
    }

    float* sb = g_s + (size_t)b * Tt * Nn;
#pragma unroll
    for (int mt = 0; mt < 2; mt++) {
        const int r0 = mb + mt * 16 + g;
#pragma unroll
        for (int nt = 0; nt < 4; nt++) {
            const int col = n0 + nb + nt * 8 + 2 * tig;
            float2 lo, hi;
            lo.x = acc[mt][nt][0]; lo.y = acc[mt][nt][1];
            hi.x = acc[mt][nt][2]; hi.y = acc[mt][nt][3];
            *(float2*)&sb[(size_t)r0 * Nn + col]       = lo;
            *(float2*)&sb[(size_t)(r0 + 8) * Nn + col] = hi;
        }
    }
}

// ---------------------------------------------------------------------------
// K3: softmax over n (1024), in-place on g_s
// ---------------------------------------------------------------------------
__global__ __launch_bounds__(256) void k3_softmax() {
    const int row = blockIdx.x;
    float* s = g_s + (size_t)row * Nn;
    const int tid = threadIdx.x;
    const int w = tid >> 5, l = tid & 31;

    float4 x = *(float4*)&s[tid * 4];
    float m = fmaxf(fmaxf(x.x, x.y), fmaxf(x.z, x.w));
#pragma unroll
    for (int o = 16; o > 0; o >>= 1) m = fmaxf(m, __shfl_xor_sync(0xffffffffu, m, o));

    __shared__ float redm[8];
    __shared__ float reds[8];
    if (l == 0) redm[w] = m;
    __syncthreads();
    float mx = redm[0];
#pragma unroll
    for (int i = 1; i < 8; i++) mx = fmaxf(mx, redm[i]);

    float e0 = __expf(x.x - mx), e1 = __expf(x.y - mx);
    float e2 = __expf(x.z - mx), e3 = __expf(x.w - mx);
    float sum = e0 + e1 + e2 + e3;
#pragma unroll
    for (int o = 16; o > 0; o >>= 1) sum += __shfl_xor_sync(0xffffffffu, sum, o);
    if (l == 0) reds[w] = sum;
    __syncthreads();
    float tot = 0.0f;
#pragma unroll
    for (int i = 0; i < 8; i++) tot += reds[i];
    const float inv = 1.0f / tot;

    float4 o;
    o.x = e0 * inv; o.y = e1 * inv; o.z = e2 * inv; o.w = e3 * inv;
    *(float4*)&s[tid * 4] = o;
}

// ---------------------------------------------------------------------------
// K_m (mma tf32, 3-term split, full ldmatrix A+B, natural layouts):
// m_part[nh][b,d,t] = sum_{n in half} f[d,n] * alpha[t,n]
// block 256 thr, tile 128d x 64t, K-chunk 16 n, 32 chunks, double-buffered
// dynamic smem: A[2][2][128][20] + B[2][2][64][20] = 61440 B
// ---------------------------------------------------------------------------
#define KM_SMEM 61440
__global__ __launch_bounds__(256) void k_m(const float* __restrict__ f) {
    extern __shared__ uint32_t dsm[];
    uint32_t (*A)[2][128][20] = (uint32_t(*)[2][128][20])dsm;            // 10240 words
    uint32_t (*Bm)[2][64][20] = (uint32_t(*)[2][64][20])(dsm + 10240);   // 5120 words
    const int b  = blockIdx.z;
    const int nh = blockIdx.y;
    const int d0 = blockIdx.x * 128;
    const int tid = threadIdx.x;
    const int w = tid >> 5, lane = tid & 31;
    const int g = lane >> 2, tig = lane & 3;
    const int mb = (w & 3) * 32, nb = (w >> 2) * 32;
    const int a_row = (lane & 7) + 8 * ((lane >> 3) & 1);
    const int a_col = 4 * (lane >> 4);
    const int b_row = (lane & 7) + 8 * (lane >> 4);
    const int b_col = 4 * ((lane >> 3) & 1);

    float acc[2][4][4];
#pragma unroll
    for (int mt = 0; mt < 2; mt++)
#pragma unroll
        for (int nt = 0; nt < 4; nt++)
#pragma unroll
            for (int i = 0; i < 4; i++) acc[mt][nt][i] = 0.0f;

    const float* fb = f   + (size_t)b * Dd * Nn + (size_t)nh * (Nn / 2);
    const float* ab = g_s + (size_t)b * Tt * Nn + (size_t)nh * (Nn / 2);

    const int fa_d = tid >> 1;           // 0..127
    const int fa_n = (tid & 1) * 8;      // 0/8
    const int al_t = tid & 63;           // 0..63
    const int al_n = (tid >> 6) * 4;     // 0,4,8,12

    float4 fv0, fv1, av;
    fv0 = *(const float4*)&fb[(size_t)(d0 + fa_d) * Nn + fa_n];
    fv1 = *(const float4*)&fb[(size_t)(d0 + fa_d) * Nn + fa_n + 4];
    av  = *(const float4*)&ab[(size_t)al_t * Nn + al_n];

    // stage chunk 0 -> buf 0
    {
        uint4 h0, l0, h1, l1;
        tf32_split(fv0.x, h0.x, l0.x); tf32_split(fv0.y, h0.y, l0.y);
        tf32_split(fv0.z, h0.z, l0.z); tf32_split(fv0.w, h0.w, l0.w);
        tf32_split(fv1.x, h1.x, l1.x); tf32_split(fv1.y, h1.y, l1.y);
        tf32_split(fv1.z, h1.z, l1.z); tf32_split(fv1.w, h1.w, l1.w);
        *(uint4*)&A[0][0][fa_d][fa_n]     = h0;
        *(uint4*)&A[0][0][fa_d][fa_n + 4] = h1;
        *(uint4*)&A[0][1][fa_d][fa_n]     = l0;
        *(uint4*)&A[0][1][fa_d][fa_n + 4] = l1;
        uint4 bh, bl;
        tf32_split(av.x, bh.x, bl.x); tf32_split(av.y, bh.y, bl.y);
        tf32_split(av.z, bh.z, bl.z); tf32_split(av.w, bh.w, bl.w);
        *(uint4*)&Bm[0][0][al_t][al_n] = bh;
        *(uint4*)&Bm[0][1][al_t][al_n] = bl;
    }
    __syncthreads();

    int p = 0;
    for (int c = 0; c < 32; c++) {
        if (c < 31) {
            const int n0n = (c + 1) * 16;
            fv0 = *(const float4*)&fb[(size_t)(d0 + fa_d) * Nn + n0n + fa_n];
            fv1 = *(const float4*)&fb[(size_t)(d0 + fa_d) * Nn + n0n + fa_n + 4];
            av  = *(const float4*)&ab[(size_t)al_t * Nn + n0n + al_n];
        }
        // compute buf p
        {
            const uint32_t ah_s = s2u(&A[p][0][0][0]);
            const uint32_t al_s = s2u(&A[p][1][0][0]);
            const uint32_t bh_s = s2u(&Bm[p][0][0][0]);
            const uint32_t bl_s = s2u(&Bm[p][1][0][0]);
#pragma unroll
            for (int ks = 0; ks < 2; ks++) {
                const int k0 = ks * 8;
                uint32_t ah[2][4], al_[2][4];
#pragma unroll
                for (int mt = 0; mt < 2; mt++) {
                    const uint32_t off = 4u * ((mb + mt * 16 + a_row) * 20 + k0 + a_col);
                    ldsm4(ah[mt],  ah_s + off);
                    ldsm4(al_[mt], al_s + off);
                }
#pragma unroll
                for (int q = 0; q < 2; q++) {
                    const uint32_t offb = 4u * ((nb + q * 16 + b_row) * 20 + k0 + b_col);
                    uint32_t bh4[4], bl4[4];
                    ldsm4(bh4, bh_s + offb);
                    ldsm4(bl4, bl_s + offb);
#pragma unroll
                    for (int j = 0; j < 2; j++) {
                        const int nt = q * 2 + j;
#pragma unroll
                        for (int mt = 0; mt < 2; mt++) {
                            mma_tf32(acc[mt][nt], ah[mt],  bh4 + 2 * j);
                            mma_tf32(acc[mt][nt], ah[mt],  bl4 + 2 * j);
                            mma_tf32(acc[mt][nt], al_[mt], bh4 + 2 * j);
                        }
                    }
                }
            }
        }
        if (c < 31) {
            const int q = p ^ 1;
            uint4 h0, l0, h1, l1;
            tf32_split(fv0.x, h0.x, l0.x); tf32_split(fv0.y, h0.y, l0.y);
            tf32_split(fv0.z, h0.z, l0.z); tf32_split(fv0.w, h0.w, l0.w);
            tf32_split(fv1.x, h1.x, l1.x); tf32_split(fv1.y, h1.y, l1.y);
            tf32_split(fv1.z, h1.z, l1.z); tf32_split(fv1.w, h1.w, l1.w);
            *(uint4*)&A[q][0][fa_d][fa_n]     = h0;
            *(uint4*)&A[q][0][fa_d][fa_n + 4] = h1;
            *(uint4*)&A[q][1][fa_d][fa_n]     = l0;
            *(uint4*)&A[q][1][fa_d][fa_n + 4] = l1;
            uint4 bh, bl;
            tf32_split(av.x, bh.x, bl.x); tf32_split(av.y, bh.y, bl.y);
            tf32_split(av.z, bh.z, bl.z); tf32_split(av.w, bh.w, bl.w);
            *(uint4*)&Bm[q][0][al_t][al_n] = bh;
            *(uint4*)&Bm[q][1][al_t][al_n] = bl;
        }
        __syncthreads();
        p ^= 1;
    }

    float* mb_out = g_mp[nh] + (size_t)b * Dd * Tt;
#pragma unroll
    for (int mt = 0; mt < 2; mt++) {
        const int r0 = d0 + mb + mt * 16 + g;
#pragma unroll
        for (int nt = 0; nt < 4; nt++) {
            const int col = nb + nt * 8 + 2 * tig;
            float2 lo, hi;
            lo.x = acc[mt][nt][0]; lo.y = acc[mt][nt][1];
            hi.x = acc[mt][nt][2]; hi.y = acc[mt][nt][3];
            *(float2*)&mb_out[(size_t)r0 * Tt + col]       = lo;
            *(float2*)&mb_out[(size_t)(r0 + 8) * Tt + col] = hi;
        }
    }
}

// ---------------------------------------------------------------------------
// K_c: c[b,k,t] = sum_d W[d,k] * (m0+m1)[b,d,t] + bias[k]   (FFMA2)
// ---------------------------------------------------------------------------
__global__ __launch_bounds__(256) void k_c(const float* __restrict__ W,
                                           const float* __restrict__ bias) {
    __shared__ __align__(16) float Wt[8][68];
    __shared__ __align__(16) float Ms[8][68];
    const int b  = blockIdx.y;
    const int k0 = blockIdx.x * 64;
    const int tid = threadIdx.x;
    const int tx = tid & 15, ty = tid >> 4;

    ull acc[4][2];
#pragma unroll
    for (int i = 0; i < 4; i++) { acc[i][0] = 0ULL; acc[i][1] = 0ULL; }

    const float* mb0 = g_mp[0] + (size_t)b * Dd * Tt;
    const float* mb1 = g_mp[1] + (size_t)b * Dd * Tt;
    const int dd = tid >> 5;
    const int cc = (tid & 31) * 2;

    for (int d0 = 0; d0 < Dd; d0 += 8) {
        *(float2*)&Wt[dd][cc] = *(const float2*)&W[(size_t)(d0 + dd) * Kk + k0 + cc];
        float2 ma = *(const float2*)&mb0[(size_t)(d0 + dd) * Tt + cc];
        float2 mc = *(const float2*)&mb1[(size_t)(d0 + dd) * Tt + cc];
        Ms[dd][cc] = ma.x + mc.x; Ms[dd][cc + 1] = ma.y + mc.y;
        __syncthreads();
#pragma unroll
        for (int d = 0; d < 8; d++) {
            float4 a4 = *(float4*)&Wt[d][ty * 4];
            ull ad[4] = {dup2(a4.x), dup2(a4.y), dup2(a4.z), dup2(a4.w)};
            ulonglong2 bp = *(ulonglong2*)&Ms[d][tx * 4];
#pragma unroll
            for (int i = 0; i < 4; i++) {
                ffma2(acc[i][0], ad[i], bp.x);
                ffma2(acc[i][1], ad[i], bp.y);
            }
        }
        __syncthreads();
    }

    float* cb = g_c + (size_t)b * Kk * Tt;
#pragma unroll
    for (int i = 0; i < 4; i++) {
        const int k = k0 + ty * 4 + i;
        const float bi = bias[k];
        float2 p0 = unpk(acc[i][0]), p1 = unpk(acc[i][1]);
        float4 o;
        o.x = p0.x + bi; o.y = p0.y + bi; o.z = p1.x + bi; o.w = p1.y + bi;
        *(float4*)&cb[(size_t)k * Tt + tx * 4] = o;
    }
}

// ---------------------------------------------------------------------------
// K5: per-token norms
// ---------------------------------------------------------------------------
__global__ __launch_bounds__(256) void k5_norms(const float* __restrict__ e) {
    __shared__ float re[4][64];
    __shared__ float rc[4][64];
    const int b = blockIdx.x;
    const int tid = threadIdx.x;
    const int t = tid & 63, q = tid >> 6;
    const float* eb = e   + (size_t)b * Kk * Tt;
    const float* cb = g_c + (size_t)b * Kk * Tt;
    float se = 0.0f, sc = 0.0f;
    for (int k = q * 64; k < q * 64 + 64; k++) {
        float x = eb[k * Tt + t]; se = fmaf(x, x, se);
        float y = cb[k * Tt + t]; sc = fmaf(y, y, sc);
    }
    re[q][t] = se; rc[q][t] = sc;
    __syncthreads();
    if (tid < 64) {
        float a = re[0][tid] + re[1][tid] + re[2][tid] + re[3][tid];
        float d = rc[0][tid] + rc[1][tid] + rc[2][tid] + rc[3][tid];
        g_le[b * Tt + tid] = sqrtf(a);
        g_lc[b * Tt + tid] = sqrtf(d);
    }
}

// ---------------------------------------------------------------------------
// K6: cos[b,i,j] = (sum_k c[b,k,i]*e[b,k,j]) / (lc[i]*le[j])
// ---------------------------------------------------------------------------
__global__ __launch_bounds__(256) void k6_cos(const float* __restrict__ e,
                                              float* __restrict__ out) {
    __shared__ __align__(16) float Cs[16][36];
    __shared__ __align__(16) float Es[16][68];
    const int ih = blockIdx.x;
    const int b  = blockIdx.y;
    const int tid = threadIdx.x;
    const int tx = tid & 15, ty = tid >> 4;

    ull acc[2][2];
    acc[0][0] = acc[0][1] = acc[1][0] = acc[1][1] = 0ULL;

    const float* cb = g_c + (size_t)b * Kk * Tt;
    const float* eb = e   + (size_t)b * Kk * Tt;
    const int lk = tid >> 4;
    const int ltE = (tid & 15) * 4;
    const int ltC = (tid & 15) * 2;

    for (int k0 = 0; k0 < Kk; k0 += 16) {
        *(float2*)&Cs[lk][ltC] = *(const float2*)&cb[(k0 + lk) * Tt + ih * 32 + ltC];
        *(float4*)&Es[lk][ltE] = *(const float4*)&eb[(k0 + lk) * Tt + ltE];
        __syncthreads();
#pragma unroll
        for (int kk = 0; kk < 16; kk++) {
            float2 a2 = *(float2*)&Cs[kk][ty * 2];
            ull ad[2] = {dup2(a2.x), dup2(a2.y)};
            ulonglong2 bp = *(ulonglong2*)&Es[kk][tx * 4];
#pragma unroll
            for (int i = 0; i < 2; i++) {
                ffma2(acc[i][0], ad[i], bp.x);
                ffma2(acc[i][1], ad[i], bp.y);
            }
        }
        __syncthreads();
    }

    float lci[2], lej[4];
#pragma unroll
    for (int i = 0; i < 2; i++) lci[i] = g_lc[b * Tt + ih * 32 + ty * 2 + i];
#pragma unroll
    for (int j = 0; j < 4; j++) lej[j] = g_le[b * Tt + tx * 4 + j];

#pragma unroll
    for (int i = 0; i < 2; i++) {
        const int irow = ih * 32 + ty * 2 + i;
        float2 p0 = unpk(acc[i][0]), p1 = unpk(acc[i][1]);
        float4 o;
        o.x = p0.x / (lci[i] * lej[0]);
        o.y = p0.y / (lci[i] * lej[1]);
        o.z = p1.x / (lci[i] * lej[2]);
        o.w = p1.y / (lci[i] * lej[3]);
        *(float4*)&out[((size_t)b * Tt + irow) * Tt + tx * 4] = o;
    }
}

// ---------------------------------------------------------------------------
extern "C" void kernel_launch(void* const* d_in, const int* in_sizes, int n_in,
                              void* d_out, int out_size) {
    const float* e     = (const float*)d_in[0];
    const float* f     = (const float*)d_in[1];
    const float* gamma = (const float*)d_in[2];
    const float* W     = (const float*)d_in[3];
    const float* bias  = (const float*)d_in[4];
    float* out = (float*)d_out;

    cudaFuncSetAttribute(k_s, cudaFuncAttributeMaxDynamicSharedMemorySize, KS_SMEM);
    cudaFuncSetAttribute(k_m, cudaFuncAttributeMaxDynamicSharedMemorySize, KM_SMEM);

    k_u<<<dim3(Dd / 128, Bb), 256>>>(e, W, gamma);
    k_s<<<dim3(Nn / 128, Bb), 256, KS_SMEM>>>(f);
    k3_softmax<<<Bb * Tt, 256>>>();
    k_m<<<dim3(Dd / 128, 2, Bb), 256, KM_SMEM>>>(f);
    k_c<<<dim3(Kk / 64, Bb), 256>>>(W, bias);
    k5_norms<<<Bb, 256>>>(e);
    k6_cos<<<dim3(2, Bb), 256>>>(e, out);
}